// round 1
// baseline (speedup 1.0000x reference)
#include <cuda_runtime.h>
#include <math.h>

// ---------------- problem constants ----------------
#define LNUM 4
#define BB   4
#define TT   1024
#define CC   768
#define NH   12
#define HD   64
#define HID  3072
#define MM   (BB*TT)          // 4096 rows
#define EPS_LN 1e-5f

// ---------------- scratch (device globals; no allocation allowed) ----------------
__device__ float g_res[(size_t)MM*CC];
__device__ float g_ln [(size_t)MM*CC];
__device__ float g_q  [(size_t)MM*CC];
__device__ float g_k  [(size_t)MM*CC];
__device__ float g_v  [(size_t)MM*CC];
__device__ float g_y  [(size_t)MM*CC];
__device__ float g_h1 [(size_t)MM*HID];

// ---------------- copy kernel (float4) ----------------
__global__ void copy4_kernel(float4* __restrict__ dst, const float4* __restrict__ src, int n4) {
    int i = blockIdx.x * blockDim.x + threadIdx.x;
    if (i < n4) dst[i] = src[i];
}

// ---------------- layernorm ----------------
__global__ void ln_kernel(const float* __restrict__ x, const float* __restrict__ g,
                          const float* __restrict__ b, float* __restrict__ out) {
    __shared__ float red0[8], red1[8];
    int row = blockIdx.x;
    int tid = threadIdx.x;
    const float* xr = x + (size_t)row * CC;
    float s = 0.f, s2 = 0.f;
    for (int i = tid; i < CC; i += 256) { float v = xr[i]; s += v; s2 += v * v; }
    for (int o = 16; o; o >>= 1) {
        s  += __shfl_xor_sync(0xffffffffu, s,  o);
        s2 += __shfl_xor_sync(0xffffffffu, s2, o);
    }
    if ((tid & 31) == 0) { red0[tid >> 5] = s; red1[tid >> 5] = s2; }
    __syncthreads();
    if (tid < 32) {
        s  = (tid < 8) ? red0[tid] : 0.f;
        s2 = (tid < 8) ? red1[tid] : 0.f;
        for (int o = 4; o; o >>= 1) {
            s  += __shfl_xor_sync(0xffffffffu, s,  o);
            s2 += __shfl_xor_sync(0xffffffffu, s2, o);
        }
        if (tid == 0) { red0[0] = s; red1[0] = s2; }
    }
    __syncthreads();
    float mu  = red0[0] * (1.f / CC);
    float var = red1[0] * (1.f / CC) - mu * mu;
    float rs  = rsqrtf(var + EPS_LN);
    float* outr = out + (size_t)row * CC;
    for (int i = tid; i < CC; i += 256)
        outr[i] = (xr[i] - mu) * rs * g[i] + b[i];
}

// ---------------- fp32 SGEMM, 128x128x16, 256 threads, 8x8 per thread ----------------
#define BM 128
#define BN 128
#define BK 16
#define AS_STR 132
// epilogue modes
#define EPI_BIAS  0
#define EPI_RESID 1
#define EPI_GELU  2

template <int EPI>
__global__ __launch_bounds__(256)
void sgemm_kernel(const float* __restrict__ A, const float* __restrict__ Bw,
                  const float* __restrict__ bias, const float* __restrict__ resid,
                  float* __restrict__ C, int Ndim, int Kdim) {
    __shared__ float As[BK * AS_STR];
    __shared__ float Bs[BK * BN];
    int tid = threadIdx.x;
    int bm = blockIdx.y * BM;
    int bn = blockIdx.x * BN;
    int tx = tid & 15, ty = tid >> 4;

    int arow = tid >> 2;            // 0..63
    int acol = (tid & 3) * 4;       // 0,4,8,12
    int brow = tid >> 5;            // 0..7
    int bcol = (tid & 31) * 4;      // 0..124

    float acc[8][8];
#pragma unroll
    for (int i = 0; i < 8; i++)
#pragma unroll
        for (int j = 0; j < 8; j++) acc[i][j] = 0.f;

    for (int k0 = 0; k0 < Kdim; k0 += BK) {
#pragma unroll
        for (int r = 0; r < 2; r++) {
            float4 av = *(const float4*)(A + (size_t)(bm + arow + r * 64) * Kdim + k0 + acol);
            As[(acol + 0) * AS_STR + arow + r * 64] = av.x;
            As[(acol + 1) * AS_STR + arow + r * 64] = av.y;
            As[(acol + 2) * AS_STR + arow + r * 64] = av.z;
            As[(acol + 3) * AS_STR + arow + r * 64] = av.w;
        }
#pragma unroll
        for (int r = 0; r < 2; r++) {
            float4 bv = *(const float4*)(Bw + (size_t)(k0 + brow + r * 8) * Ndim + bn + bcol);
            *(float4*)(Bs + (brow + r * 8) * BN + bcol) = bv;
        }
        __syncthreads();
#pragma unroll
        for (int kk = 0; kk < BK; kk++) {
            float4 a0 = *(const float4*)(As + kk * AS_STR + ty * 8);
            float4 a1 = *(const float4*)(As + kk * AS_STR + ty * 8 + 4);
            float4 b0 = *(const float4*)(Bs + kk * BN + tx * 8);
            float4 b1 = *(const float4*)(Bs + kk * BN + tx * 8 + 4);
            float a[8] = {a0.x, a0.y, a0.z, a0.w, a1.x, a1.y, a1.z, a1.w};
            float b[8] = {b0.x, b0.y, b0.z, b0.w, b1.x, b1.y, b1.z, b1.w};
#pragma unroll
            for (int i = 0; i < 8; i++)
#pragma unroll
                for (int j = 0; j < 8; j++) acc[i][j] += a[i] * b[j];
        }
        __syncthreads();
    }

#pragma unroll
    for (int i = 0; i < 8; i++) {
        int row = bm + ty * 8 + i;
#pragma unroll
        for (int j = 0; j < 8; j++) {
            int col = bn + tx * 8 + j;
            float v = acc[i][j] + bias[col];
            if (EPI == EPI_RESID) v += resid[(size_t)row * Ndim + col];
            if (EPI == EPI_GELU)  v = v * 0.5f * (1.0f + erff(v * 0.70710678118654752f));
            C[(size_t)row * Ndim + col] = v;
        }
    }
}

// ---------------- fused attention (flash-style, 64 q-rows per block) ----------------
#define AT_STR 65
#define ATTN_SMEM ((4 * 64 * AT_STR + 3 * 64) * (int)sizeof(float))

__global__ __launch_bounds__(256)
void attn_kernel(const float* __restrict__ Q, const float* __restrict__ K,
                 const float* __restrict__ V, float* __restrict__ Y) {
    extern __shared__ float sm[];
    float* Qs = sm;                     // 64 x 65
    float* Ks = Qs + 64 * AT_STR;       // 64 x 65
    float* Vs = Ks + 64 * AT_STR;       // 64 x 65
    float* Ps = Vs + 64 * AT_STR;       // 64 x 65
    float* mS = Ps + 64 * AT_STR;       // 64
    float* lS = mS + 64;                // 64
    float* aS = lS + 64;                // 64

    int tid = threadIdx.x;
    int qb  = blockIdx.x * 64;
    int bh  = blockIdx.y;
    int b   = bh / NH, h = bh % NH;
    size_t base = (size_t)b * TT * CC + (size_t)h * HD;

    // load Q tile
    for (int i = tid; i < 64 * 64; i += 256) {
        int r = i >> 6, d = i & 63;
        Qs[r * AT_STR + d] = Q[base + (size_t)(qb + r) * CC + d];
    }
    if (tid < 64) { mS[tid] = -1e30f; lS[tid] = 0.f; }

    int tx = tid & 15, ty = tid >> 4;
    float o[4][4];
#pragma unroll
    for (int i = 0; i < 4; i++)
#pragma unroll
        for (int j = 0; j < 4; j++) o[i][j] = 0.f;

    int qmod = qb & 255;
    int srow = tid >> 2, sseg = tid & 3;

    for (int kb = 0; kb < TT; kb += 64) {
        if ((kb & 255) > qmod + 63) continue;   // tile fully masked for all rows
        __syncthreads();                        // protect smem reuse; 1st iter: Q/m/l init
        for (int i = tid; i < 64 * 64; i += 256) {
            int r = i >> 6, d = i & 63;
            Ks[r * AT_STR + d] = K[base + (size_t)(kb + r) * CC + d];
            Vs[r * AT_STR + d] = V[base + (size_t)(kb + r) * CC + d];
        }
        __syncthreads();

        // S = Q K^T  (4x4 per thread)
        float s[4][4];
#pragma unroll
        for (int i = 0; i < 4; i++)
#pragma unroll
            for (int j = 0; j < 4; j++) s[i][j] = 0.f;
        for (int d = 0; d < 64; d++) {
            float a0 = Qs[(ty * 4 + 0) * AT_STR + d];
            float a1 = Qs[(ty * 4 + 1) * AT_STR + d];
            float a2 = Qs[(ty * 4 + 2) * AT_STR + d];
            float a3 = Qs[(ty * 4 + 3) * AT_STR + d];
            float c0 = Ks[(tx * 4 + 0) * AT_STR + d];
            float c1 = Ks[(tx * 4 + 1) * AT_STR + d];
            float c2 = Ks[(tx * 4 + 2) * AT_STR + d];
            float c3 = Ks[(tx * 4 + 3) * AT_STR + d];
            s[0][0] += a0 * c0; s[0][1] += a0 * c1; s[0][2] += a0 * c2; s[0][3] += a0 * c3;
            s[1][0] += a1 * c0; s[1][1] += a1 * c1; s[1][2] += a1 * c2; s[1][3] += a1 * c3;
            s[2][0] += a2 * c0; s[2][1] += a2 * c1; s[2][2] += a2 * c2; s[2][3] += a2 * c3;
            s[3][0] += a3 * c0; s[3][1] += a3 * c1; s[3][2] += a3 * c2; s[3][3] += a3 * c3;
        }
#pragma unroll
        for (int i = 0; i < 4; i++) {
            int qg = (qb + ty * 4 + i) & 255;
#pragma unroll
            for (int j = 0; j < 4; j++) {
                int kg = (kb + tx * 4 + j) & 255;
                float v = s[i][j] * 0.125f;          // 1/sqrt(64)
                if (kg > qg) v = -1e30f;
                Ps[(ty * 4 + i) * AT_STR + tx * 4 + j] = v;
            }
        }
        __syncthreads();

        // online softmax: 4 threads per row
        {
            float mx = -1e30f;
            int rbase = srow * AT_STR + sseg * 16;
#pragma unroll
            for (int k2 = 0; k2 < 16; k2++) mx = fmaxf(mx, Ps[rbase + k2]);
            mx = fmaxf(mx, __shfl_xor_sync(0xffffffffu, mx, 1));
            mx = fmaxf(mx, __shfl_xor_sync(0xffffffffu, mx, 2));
            float m_old = mS[srow];
            float m_new = fmaxf(m_old, mx);
            float sum = 0.f;
#pragma unroll
            for (int k2 = 0; k2 < 16; k2++) {
                float p = __expf(Ps[rbase + k2] - m_new);
                Ps[rbase + k2] = p;
                sum += p;
            }
            sum += __shfl_xor_sync(0xffffffffu, sum, 1);
            sum += __shfl_xor_sync(0xffffffffu, sum, 2);
            if (sseg == 0) {
                float alpha = __expf(m_old - m_new);
                lS[srow] = lS[srow] * alpha + sum;
                mS[srow] = m_new;
                aS[srow] = alpha;
            }
        }
        __syncthreads();

        // O = O*alpha + P V
#pragma unroll
        for (int i = 0; i < 4; i++) {
            float al = aS[ty * 4 + i];
#pragma unroll
            for (int j = 0; j < 4; j++) o[i][j] *= al;
        }
        for (int k2 = 0; k2 < 64; k2++) {
            float p0 = Ps[(ty * 4 + 0) * AT_STR + k2];
            float p1 = Ps[(ty * 4 + 1) * AT_STR + k2];
            float p2 = Ps[(ty * 4 + 2) * AT_STR + k2];
            float p3 = Ps[(ty * 4 + 3) * AT_STR + k2];
            float v0 = Vs[k2 * AT_STR + tx * 4 + 0];
            float v1 = Vs[k2 * AT_STR + tx * 4 + 1];
            float v2 = Vs[k2 * AT_STR + tx * 4 + 2];
            float v3 = Vs[k2 * AT_STR + tx * 4 + 3];
            o[0][0] += p0 * v0; o[0][1] += p0 * v1; o[0][2] += p0 * v2; o[0][3] += p0 * v3;
            o[1][0] += p1 * v0; o[1][1] += p1 * v1; o[1][2] += p1 * v2; o[1][3] += p1 * v3;
            o[2][0] += p2 * v0; o[2][1] += p2 * v1; o[2][2] += p2 * v2; o[2][3] += p2 * v3;
            o[3][0] += p3 * v0; o[3][1] += p3 * v1; o[3][2] += p3 * v2; o[3][3] += p3 * v3;
        }
    }

    // write Y
#pragma unroll
    for (int i = 0; i < 4; i++) {
        float inv = 1.0f / lS[ty * 4 + i];
        size_t rowoff = base + (size_t)(qb + ty * 4 + i) * CC + tx * 4;
#pragma unroll
        for (int j = 0; j < 4; j++) Y[rowoff + j] = o[i][j] * inv;
    }
}

// ---------------- host orchestration ----------------
extern "C" void kernel_launch(void* const* d_in, const int* in_sizes, int n_in,
                              void* d_out, int out_size) {
    const float* x     = (const float*)d_in[0];
    const float* ln1_g = (const float*)d_in[1];
    const float* ln1_b = (const float*)d_in[2];
    const float* Wq    = (const float*)d_in[3];
    const float* bq    = (const float*)d_in[4];
    const float* Wk    = (const float*)d_in[5];
    const float* bk    = (const float*)d_in[6];
    const float* Wv    = (const float*)d_in[7];
    const float* bv    = (const float*)d_in[8];
    const float* Wp    = (const float*)d_in[9];
    const float* bp    = (const float*)d_in[10];
    const float* ln2_g = (const float*)d_in[11];
    const float* ln2_b = (const float*)d_in[12];
    const float* W1    = (const float*)d_in[13];
    const float* b1    = (const float*)d_in[14];
    const float* W2    = (const float*)d_in[15];
    const float* b2    = (const float*)d_in[16];

    float *res, *ln, *q, *k, *v, *y, *h1;
    cudaGetSymbolAddress((void**)&res, g_res);
    cudaGetSymbolAddress((void**)&ln,  g_ln);
    cudaGetSymbolAddress((void**)&q,   g_q);
    cudaGetSymbolAddress((void**)&k,   g_k);
    cudaGetSymbolAddress((void**)&v,   g_v);
    cudaGetSymbolAddress((void**)&y,   g_y);
    cudaGetSymbolAddress((void**)&h1,  g_h1);

    cudaFuncSetAttribute(attn_kernel, cudaFuncAttributeMaxDynamicSharedMemorySize, ATTN_SMEM);

    // residual = x
    {
        int n4 = (MM * CC) / 4;
        copy4_kernel<<<(n4 + 255) / 256, 256>>>((float4*)res, (const float4*)x, n4);
    }

    dim3 gemm_qkv((CC + BN - 1) / BN, MM / BM);     // 6 x 32
    dim3 gemm_h  ((HID + BN - 1) / BN, MM / BM);    // 24 x 32
    dim3 attn_grid(TT / 64, BB * NH);               // 16 x 48

    for (int l = 0; l < LNUM; l++) {
        const float* wq = Wq + (size_t)l * CC * CC;
        const float* wk = Wk + (size_t)l * CC * CC;
        const float* wv = Wv + (size_t)l * CC * CC;
        const float* wp = Wp + (size_t)l * CC * CC;
        const float* w1 = W1 + (size_t)l * CC * HID;
        const float* w2 = W2 + (size_t)l * HID * CC;

        // LN1
        ln_kernel<<<MM, 256>>>(res, ln1_g + (size_t)l * CC, ln1_b + (size_t)l * CC, ln);
        // Q, K, V
        sgemm_kernel<EPI_BIAS><<<gemm_qkv, 256>>>(ln, wq, bq + (size_t)l * CC, nullptr, q, CC, CC);
        sgemm_kernel<EPI_BIAS><<<gemm_qkv, 256>>>(ln, wk, bk + (size_t)l * CC, nullptr, k, CC, CC);
        sgemm_kernel<EPI_BIAS><<<gemm_qkv, 256>>>(ln, wv, bv + (size_t)l * CC, nullptr, v, CC, CC);
        // attention
        attn_kernel<<<attn_grid, 256, ATTN_SMEM>>>(q, k, v, y);
        // residual += y @ Wp + bp
        sgemm_kernel<EPI_RESID><<<gemm_qkv, 256>>>(y, wp, bp + (size_t)l * CC, res, res, CC, CC);
        // LN2
        ln_kernel<<<MM, 256>>>(res, ln2_g + (size_t)l * CC, ln2_b + (size_t)l * CC, ln);
        // h1 = gelu(ln @ W1 + b1)
        sgemm_kernel<EPI_GELU><<<gemm_h, 256>>>(ln, w1, b1 + (size_t)l * HID, nullptr, h1, HID, CC);
        // residual += h1 @ W2 + b2
        sgemm_kernel<EPI_RESID><<<gemm_qkv, 256>>>(h1, w2, b2 + (size_t)l * CC, res, res, CC, HID);
    }

    // output
    {
        int n4 = (MM * CC) / 4;
        copy4_kernel<<<(n4 + 255) / 256, 256>>>((float4*)d_out, (const float4*)res, n4);
    }
}

// round 3
// speedup vs baseline: 1.9336x; 1.9336x over previous
#include <cuda_runtime.h>
#include <math.h>
#include <cstdint>

// ---------------- problem constants ----------------
#define LNUM 4
#define BB   4
#define TT   1024
#define CC   768
#define NH   12
#define HD   64
#define HID  3072
#define MM   (BB*TT)          // 4096 rows
#define EPS_LN 1e-5f

// ---------------- scratch (device globals; no allocation allowed) ----------------
__device__ float g_res[(size_t)MM*CC];
__device__ float g_ln [(size_t)MM*CC];
__device__ float g_q  [(size_t)MM*CC];
__device__ float g_k  [(size_t)MM*CC];
__device__ float g_v  [(size_t)MM*CC];
__device__ float g_y  [(size_t)MM*CC];
__device__ float g_h1 [(size_t)MM*HID];
#define WT_PER_LAYER (4*CC*CC + 2*CC*HID)
__device__ float g_wt [(size_t)LNUM * WT_PER_LAYER];

// ---------------- copy kernel (float4) ----------------
__global__ void copy4_kernel(float4* __restrict__ dst, const float4* __restrict__ src, int n4) {
    int i = blockIdx.x * blockDim.x + threadIdx.x;
    if (i < n4) dst[i] = src[i];
}

// ---------------- transpose: src[H,W] -> dst[W,H] ----------------
__global__ void transpose_kernel(const float* __restrict__ src, float* __restrict__ dst,
                                 int H, int W) {
    __shared__ float tile[32][33];
    int tx = threadIdx.x, ty = threadIdx.y;
    int xs = blockIdx.x * 32 + tx;
    int ys = blockIdx.y * 32 + ty;
#pragma unroll
    for (int i = 0; i < 32; i += 8)
        tile[ty + i][tx] = src[(size_t)(ys + i) * W + xs];
    __syncthreads();
    int xd = blockIdx.y * 32 + tx;
    int yd = blockIdx.x * 32 + ty;
#pragma unroll
    for (int i = 0; i < 32; i += 8)
        dst[(size_t)(yd + i) * H + xd] = tile[tx][ty + i];
}

// ---------------- layernorm ----------------
__global__ void ln_kernel(const float* __restrict__ x, const float* __restrict__ g,
                          const float* __restrict__ b, float* __restrict__ out) {
    __shared__ float red0[8], red1[8];
    int row = blockIdx.x;
    int tid = threadIdx.x;
    const float* xr = x + (size_t)row * CC;
    float s = 0.f, s2 = 0.f;
    for (int i = tid; i < CC; i += 256) { float v = xr[i]; s += v; s2 += v * v; }
    for (int o = 16; o; o >>= 1) {
        s  += __shfl_xor_sync(0xffffffffu, s,  o);
        s2 += __shfl_xor_sync(0xffffffffu, s2, o);
    }
    if ((tid & 31) == 0) { red0[tid >> 5] = s; red1[tid >> 5] = s2; }
    __syncthreads();
    if (tid < 32) {
        s  = (tid < 8) ? red0[tid] : 0.f;
        s2 = (tid < 8) ? red1[tid] : 0.f;
        for (int o = 4; o; o >>= 1) {
            s  += __shfl_xor_sync(0xffffffffu, s,  o);
            s2 += __shfl_xor_sync(0xffffffffu, s2, o);
        }
        if (tid == 0) { red0[0] = s; red1[0] = s2; }
    }
    __syncthreads();
    float mu  = red0[0] * (1.f / CC);
    float var = red1[0] * (1.f / CC) - mu * mu;
    float rs  = rsqrtf(var + EPS_LN);
    float* outr = out + (size_t)row * CC;
    for (int i = tid; i < CC; i += 256)
        outr[i] = (xr[i] - mu) * rs * g[i] + b[i];
}

// ---------------- tf32 mma.sync GEMM ----------------
// C[M,N] = A[M,K] @ Bt[N,K]^T (+bias, +resid / gelu)
// tile 128x128x16, 256 threads (8 warps), warp = 64x32, mma m16n8k8.
#define EPI_BIAS  0
#define EPI_RESID 1
#define EPI_GELU  2

#define TSTR 20   // padded row stride in words for 16-wide k-slab

__device__ __forceinline__ uint32_t f2tf32(float x) {
    uint32_t u;
    asm("cvt.rna.tf32.f32 %0, %1;" : "=r"(u) : "f"(x));
    return u;
}

template <int EPI>
__global__ __launch_bounds__(256)
void tc_gemm_kernel(const float* __restrict__ A, const float* __restrict__ Bt,
                    const float* __restrict__ bias, const float* __restrict__ resid,
                    float* __restrict__ C, int Ndim, int Kdim) {
    __shared__ uint32_t As[128 * TSTR];
    __shared__ uint32_t Bs[128 * TSTR];
    __shared__ float sBias[128];

    int tid = threadIdx.x;
    int lane = tid & 31;
    int wid = tid >> 5;
    int bm = blockIdx.y * 128, bn = blockIdx.x * 128;

    if (tid < 128) sBias[tid] = bias[bn + tid];

    int lr = lane >> 2;    // 0..7
    int lc = lane & 3;     // 0..3
    int wm = (wid & 1) * 64;
    int wn = (wid >> 1) * 32;

    // global load mapping: thread t covers rows (t>>2) and (t>>2)+64, colgroup (t&3)*4
    int grow = tid >> 2;
    int gcg  = (tid & 3) * 4;

    float acc[4][4][4];
#pragma unroll
    for (int i = 0; i < 4; i++)
#pragma unroll
        for (int j = 0; j < 4; j++)
#pragma unroll
            for (int r = 0; r < 4; r++) acc[i][j][r] = 0.f;

    int nch = Kdim >> 4;
    const float* aP0 = A  + (size_t)(bm + grow) * Kdim + gcg;
    const float* aP1 = A  + (size_t)(bm + grow + 64) * Kdim + gcg;
    const float* bP0 = Bt + (size_t)(bn + grow) * Kdim + gcg;
    const float* bP1 = Bt + (size_t)(bn + grow + 64) * Kdim + gcg;

    float4 pa0 = *(const float4*)aP0;
    float4 pa1 = *(const float4*)aP1;
    float4 pb0 = *(const float4*)bP0;
    float4 pb1 = *(const float4*)bP1;

    for (int c = 0; c < nch; c++) {
        // store (with tf32 convert) into smem
        {
            uint4 ua0 = make_uint4(f2tf32(pa0.x), f2tf32(pa0.y), f2tf32(pa0.z), f2tf32(pa0.w));
            uint4 ua1 = make_uint4(f2tf32(pa1.x), f2tf32(pa1.y), f2tf32(pa1.z), f2tf32(pa1.w));
            uint4 ub0 = make_uint4(f2tf32(pb0.x), f2tf32(pb0.y), f2tf32(pb0.z), f2tf32(pb0.w));
            uint4 ub1 = make_uint4(f2tf32(pb1.x), f2tf32(pb1.y), f2tf32(pb1.z), f2tf32(pb1.w));
            *(uint4*)(As + grow * TSTR + gcg)        = ua0;
            *(uint4*)(As + (grow + 64) * TSTR + gcg) = ua1;
            *(uint4*)(Bs + grow * TSTR + gcg)        = ub0;
            *(uint4*)(Bs + (grow + 64) * TSTR + gcg) = ub1;
        }
        __syncthreads();
        if (c + 1 < nch) {
            int k0g = (c + 1) << 4;
            pa0 = *(const float4*)(aP0 + k0g);
            pa1 = *(const float4*)(aP1 + k0g);
            pb0 = *(const float4*)(bP0 + k0g);
            pb1 = *(const float4*)(bP1 + k0g);
        }
#pragma unroll
        for (int ks = 0; ks < 2; ks++) {
            int k0 = ks * 8;
            uint32_t a[4][4], b[4][2];
#pragma unroll
            for (int i = 0; i < 4; i++) {
                int r0 = wm + i * 16 + lr;
                a[i][0] = As[r0 * TSTR + k0 + lc];
                a[i][1] = As[(r0 + 8) * TSTR + k0 + lc];
                a[i][2] = As[r0 * TSTR + k0 + lc + 4];
                a[i][3] = As[(r0 + 8) * TSTR + k0 + lc + 4];
            }
#pragma unroll
            for (int j = 0; j < 4; j++) {
                int n0 = wn + j * 8 + lr;
                b[j][0] = Bs[n0 * TSTR + k0 + lc];
                b[j][1] = Bs[n0 * TSTR + k0 + lc + 4];
            }
#pragma unroll
            for (int i = 0; i < 4; i++)
#pragma unroll
                for (int j = 0; j < 4; j++) {
                    asm volatile(
                        "mma.sync.aligned.m16n8k8.row.col.f32.tf32.tf32.f32 "
                        "{%0,%1,%2,%3}, {%4,%5,%6,%7}, {%8,%9}, {%0,%1,%2,%3};"
                        : "+f"(acc[i][j][0]), "+f"(acc[i][j][1]),
                          "+f"(acc[i][j][2]), "+f"(acc[i][j][3])
                        : "r"(a[i][0]), "r"(a[i][1]), "r"(a[i][2]), "r"(a[i][3]),
                          "r"(b[j][0]), "r"(b[j][1]));
                }
        }
        __syncthreads();
    }

    // epilogue
#pragma unroll
    for (int i = 0; i < 4; i++) {
        int r0 = bm + wm + i * 16 + lr;
#pragma unroll
        for (int j = 0; j < 4; j++) {
            int colL = wn + j * 8 + lc * 2;       // local col within 128 tile
            int col = bn + colL;
            float v0 = acc[i][j][0] + sBias[colL];
            float v1 = acc[i][j][1] + sBias[colL + 1];
            float v2 = acc[i][j][2] + sBias[colL];
            float v3 = acc[i][j][3] + sBias[colL + 1];
            if (EPI == EPI_RESID) {
                float2 ra = *(const float2*)(resid + (size_t)r0 * Ndim + col);
                float2 rb = *(const float2*)(resid + (size_t)(r0 + 8) * Ndim + col);
                v0 += ra.x; v1 += ra.y; v2 += rb.x; v3 += rb.y;
            }
            if (EPI == EPI_GELU) {
                v0 = v0 * 0.5f * (1.0f + erff(v0 * 0.70710678118654752f));
                v1 = v1 * 0.5f * (1.0f + erff(v1 * 0.70710678118654752f));
                v2 = v2 * 0.5f * (1.0f + erff(v2 * 0.70710678118654752f));
                v3 = v3 * 0.5f * (1.0f + erff(v3 * 0.70710678118654752f));
            }
            *(float2*)(C + (size_t)r0 * Ndim + col)       = make_float2(v0, v1);
            *(float2*)(C + (size_t)(r0 + 8) * Ndim + col) = make_float2(v2, v3);
        }
    }
}

// ---------------- fused attention (flash-style, 64 q-rows per block) ----------------
#define AT_STR 65
#define ATTN_SMEM ((4 * 64 * AT_STR + 3 * 64) * (int)sizeof(float))

__global__ __launch_bounds__(256)
void attn_kernel(const float* __restrict__ Q, const float* __restrict__ K,
                 const float* __restrict__ V, float* __restrict__ Y) {
    extern __shared__ float sm[];
    float* Qs = sm;
    float* Ks = Qs + 64 * AT_STR;
    float* Vs = Ks + 64 * AT_STR;
    float* Ps = Vs + 64 * AT_STR;
    float* mS = Ps + 64 * AT_STR;
    float* lS = mS + 64;
    float* aS = lS + 64;

    int tid = threadIdx.x;
    int qb  = blockIdx.x * 64;
    int bh  = blockIdx.y;
    int b   = bh / NH, h = bh % NH;
    size_t base = (size_t)b * TT * CC + (size_t)h * HD;

    for (int i = tid; i < 64 * 64; i += 256) {
        int r = i >> 6, d = i & 63;
        Qs[r * AT_STR + d] = Q[base + (size_t)(qb + r) * CC + d];
    }
    if (tid < 64) { mS[tid] = -1e30f; lS[tid] = 0.f; }

    int tx = tid & 15, ty = tid >> 4;
    float o[4][4];
#pragma unroll
    for (int i = 0; i < 4; i++)
#pragma unroll
        for (int j = 0; j < 4; j++) o[i][j] = 0.f;

    int qmod = qb & 255;
    int srow = tid >> 2, sseg = tid & 3;

    for (int kb = 0; kb < TT; kb += 64) {
        if ((kb & 255) > qmod + 63) continue;
        __syncthreads();
        for (int i = tid; i < 64 * 64; i += 256) {
            int r = i >> 6, d = i & 63;
            Ks[r * AT_STR + d] = K[base + (size_t)(kb + r) * CC + d];
            Vs[r * AT_STR + d] = V[base + (size_t)(kb + r) * CC + d];
        }
        __syncthreads();

        float s[4][4];
#pragma unroll
        for (int i = 0; i < 4; i++)
#pragma unroll
            for (int j = 0; j < 4; j++) s[i][j] = 0.f;
        for (int d = 0; d < 64; d++) {
            float a0 = Qs[(ty * 4 + 0) * AT_STR + d];
            float a1 = Qs[(ty * 4 + 1) * AT_STR + d];
            float a2 = Qs[(ty * 4 + 2) * AT_STR + d];
            float a3 = Qs[(ty * 4 + 3) * AT_STR + d];
            float c0 = Ks[(tx * 4 + 0) * AT_STR + d];
            float c1 = Ks[(tx * 4 + 1) * AT_STR + d];
            float c2 = Ks[(tx * 4 + 2) * AT_STR + d];
            float c3 = Ks[(tx * 4 + 3) * AT_STR + d];
            s[0][0] += a0 * c0; s[0][1] += a0 * c1; s[0][2] += a0 * c2; s[0][3] += a0 * c3;
            s[1][0] += a1 * c0; s[1][1] += a1 * c1; s[1][2] += a1 * c2; s[1][3] += a1 * c3;
            s[2][0] += a2 * c0; s[2][1] += a2 * c1; s[2][2] += a2 * c2; s[2][3] += a2 * c3;
            s[3][0] += a3 * c0; s[3][1] += a3 * c1; s[3][2] += a3 * c2; s[3][3] += a3 * c3;
        }
#pragma unroll
        for (int i = 0; i < 4; i++) {
            int qg = (qb + ty * 4 + i) & 255;
#pragma unroll
            for (int j = 0; j < 4; j++) {
                int kg = (kb + tx * 4 + j) & 255;
                float v = s[i][j] * 0.125f;
                if (kg > qg) v = -1e30f;
                Ps[(ty * 4 + i) * AT_STR + tx * 4 + j] = v;
            }
        }
        __syncthreads();

        {
            float mx = -1e30f;
            int rbase = srow * AT_STR + sseg * 16;
#pragma unroll
            for (int k2 = 0; k2 < 16; k2++) mx = fmaxf(mx, Ps[rbase + k2]);
            mx = fmaxf(mx, __shfl_xor_sync(0xffffffffu, mx, 1));
            mx = fmaxf(mx, __shfl_xor_sync(0xffffffffu, mx, 2));
            float m_old = mS[srow];
            float m_new = fmaxf(m_old, mx);
            float sum = 0.f;
#pragma unroll
            for (int k2 = 0; k2 < 16; k2++) {
                float p = __expf(Ps[rbase + k2] - m_new);
                Ps[rbase + k2] = p;
                sum += p;
            }
            sum += __shfl_xor_sync(0xffffffffu, sum, 1);
            sum += __shfl_xor_sync(0xffffffffu, sum, 2);
            if (sseg == 0) {
                float alpha = __expf(m_old - m_new);
                lS[srow] = lS[srow] * alpha + sum;
                mS[srow] = m_new;
                aS[srow] = alpha;
            }
        }
        __syncthreads();

#pragma unroll
        for (int i = 0; i < 4; i++) {
            float al = aS[ty * 4 + i];
#pragma unroll
            for (int j = 0; j < 4; j++) o[i][j] *= al;
        }
        for (int k2 = 0; k2 < 64; k2++) {
            float p0 = Ps[(ty * 4 + 0) * AT_STR + k2];
            float p1 = Ps[(ty * 4 + 1) * AT_STR + k2];
            float p2 = Ps[(ty * 4 + 2) * AT_STR + k2];
            float p3 = Ps[(ty * 4 + 3) * AT_STR + k2];
            float v0 = Vs[k2 * AT_STR + tx * 4 + 0];
            float v1 = Vs[k2 * AT_STR + tx * 4 + 1];
            float v2 = Vs[k2 * AT_STR + tx * 4 + 2];
            float v3 = Vs[k2 * AT_STR + tx * 4 + 3];
            o[0][0] += p0 * v0; o[0][1] += p0 * v1; o[0][2] += p0 * v2; o[0][3] += p0 * v3;
            o[1][0] += p1 * v0; o[1][1] += p1 * v1; o[1][2] += p1 * v2; o[1][3] += p1 * v3;
            o[2][0] += p2 * v0; o[2][1] += p2 * v1; o[2][2] += p2 * v2; o[2][3] += p2 * v3;
            o[3][0] += p3 * v0; o[3][1] += p3 * v1; o[3][2] += p3 * v2; o[3][3] += p3 * v3;
        }
    }

#pragma unroll
    for (int i = 0; i < 4; i++) {
        float inv = 1.0f / lS[ty * 4 + i];
        size_t rowoff = base + (size_t)(qb + ty * 4 + i) * CC + tx * 4;
#pragma unroll
        for (int j = 0; j < 4; j++) Y[rowoff + j] = o[i][j] * inv;
    }
}

// ---------------- host orchestration ----------------
extern "C" void kernel_launch(void* const* d_in, const int* in_sizes, int n_in,
                              void* d_out, int out_size) {
    const float* x     = (const float*)d_in[0];
    const float* ln1_g = (const float*)d_in[1];
    const float* ln1_b = (const float*)d_in[2];
    const float* Wq    = (const float*)d_in[3];
    const float* bq    = (const float*)d_in[4];
    const float* Wk    = (const float*)d_in[5];
    const float* bk    = (const float*)d_in[6];
    const float* Wv    = (const float*)d_in[7];
    const float* bv    = (const float*)d_in[8];
    const float* Wp    = (const float*)d_in[9];
    const float* bp    = (const float*)d_in[10];
    const float* ln2_g = (const float*)d_in[11];
    const float* ln2_b = (const float*)d_in[12];
    const float* W1    = (const float*)d_in[13];
    const float* b1    = (const float*)d_in[14];
    const float* W2    = (const float*)d_in[15];
    const float* b2    = (const float*)d_in[16];

    float *res, *ln, *q, *k, *v, *y, *h1, *wt;
    cudaGetSymbolAddress((void**)&res, g_res);
    cudaGetSymbolAddress((void**)&ln,  g_ln);
    cudaGetSymbolAddress((void**)&q,   g_q);
    cudaGetSymbolAddress((void**)&k,   g_k);
    cudaGetSymbolAddress((void**)&v,   g_v);
    cudaGetSymbolAddress((void**)&y,   g_y);
    cudaGetSymbolAddress((void**)&h1,  g_h1);
    cudaGetSymbolAddress((void**)&wt,  g_wt);

    cudaFuncSetAttribute(attn_kernel, cudaFuncAttributeMaxDynamicSharedMemorySize, ATTN_SMEM);

    // ---- transpose all weights into g_wt ----
    dim3 tb(32, 8);
    for (int l = 0; l < LNUM; l++) {
        float* base = wt + (size_t)l * WT_PER_LAYER;
        transpose_kernel<<<dim3(CC/32, CC/32), tb>>>(Wq + (size_t)l*CC*CC, base + 0*CC*CC, CC, CC);
        transpose_kernel<<<dim3(CC/32, CC/32), tb>>>(Wk + (size_t)l*CC*CC, base + 1*CC*CC, CC, CC);
        transpose_kernel<<<dim3(CC/32, CC/32), tb>>>(Wv + (size_t)l*CC*CC, base + 2*CC*CC, CC, CC);
        transpose_kernel<<<dim3(CC/32, CC/32), tb>>>(Wp + (size_t)l*CC*CC, base + 3*CC*CC, CC, CC);
        transpose_kernel<<<dim3(HID/32, CC/32), tb>>>(W1 + (size_t)l*CC*HID, base + 4*CC*CC, CC, HID);
        transpose_kernel<<<dim3(CC/32, HID/32), tb>>>(W2 + (size_t)l*HID*CC, base + 4*CC*CC + (size_t)CC*HID, HID, CC);
    }

    // residual = x
    {
        int n4 = (MM * CC) / 4;
        copy4_kernel<<<(n4 + 255) / 256, 256>>>((float4*)res, (const float4*)x, n4);
    }

    dim3 gemm_qkv(CC / 128, MM / 128);      // 6 x 32
    dim3 gemm_h  (HID / 128, MM / 128);     // 24 x 32
    dim3 attn_grid(TT / 64, BB * NH);       // 16 x 48

    for (int l = 0; l < LNUM; l++) {
        float* base = wt + (size_t)l * WT_PER_LAYER;
        const float* wqt = base + 0*CC*CC;
        const float* wkt = base + 1*CC*CC;
        const float* wvt = base + 2*CC*CC;
        const float* wpt = base + 3*CC*CC;
        const float* w1t = base + 4*CC*CC;
        const float* w2t = base + 4*CC*CC + (size_t)CC*HID;

        ln_kernel<<<MM, 256>>>(res, ln1_g + (size_t)l*CC, ln1_b + (size_t)l*CC, ln);
        tc_gemm_kernel<EPI_BIAS><<<gemm_qkv, 256>>>(ln, wqt, bq + (size_t)l*CC, nullptr, q, CC, CC);
        tc_gemm_kernel<EPI_BIAS><<<gemm_qkv, 256>>>(ln, wkt, bk + (size_t)l*CC, nullptr, k, CC, CC);
        tc_gemm_kernel<EPI_BIAS><<<gemm_qkv, 256>>>(ln, wvt, bv + (size_t)l*CC, nullptr, v, CC, CC);
        attn_kernel<<<attn_grid, 256, ATTN_SMEM>>>(q, k, v, y);
        tc_gemm_kernel<EPI_RESID><<<gemm_qkv, 256>>>(y, wpt, bp + (size_t)l*CC, res, res, CC, CC);
        ln_kernel<<<MM, 256>>>(res, ln2_g + (size_t)l*CC, ln2_b + (size_t)l*CC, ln);
        tc_gemm_kernel<EPI_GELU><<<gemm_h, 256>>>(ln, w1t, b1 + (size_t)l*HID, nullptr, h1, HID, CC);
        tc_gemm_kernel<EPI_RESID><<<gemm_qkv, 256>>>(h1, w2t, b2 + (size_t)l*CC, res, res, CC, HID);
    }

    {
        int n4 = (MM * CC) / 4;
        copy4_kernel<<<(n4 + 255) / 256, 256>>>((float4*)d_out, (const float4*)res, n4);
    }
}

// round 4
// speedup vs baseline: 2.1763x; 1.1255x over previous
#include <cuda_runtime.h>
#include <math.h>
#include <cstdint>

// ---------------- problem constants ----------------
#define LNUM 4
#define BB   4
#define TT   1024
#define CC   768
#define NH   12
#define HD   64
#define HID  3072
#define MM   (BB*TT)          // 4096 rows
#define EPS_LN 1e-5f

// ---------------- scratch (device globals; no allocation allowed) ----------------
__device__ float g_res[(size_t)MM*CC];
__device__ float g_ln [(size_t)MM*CC];
__device__ float g_q  [(size_t)MM*CC];
__device__ float g_k  [(size_t)MM*CC];
__device__ float g_v  [(size_t)MM*CC];
__device__ float g_y  [(size_t)MM*CC];
__device__ float g_h1 [(size_t)MM*HID];

// ---------------- copy kernel (float4) ----------------
__global__ void copy4_kernel(float4* __restrict__ dst, const float4* __restrict__ src, int n4) {
    int i = blockIdx.x * blockDim.x + threadIdx.x;
    if (i < n4) dst[i] = src[i];
}

// ---------------- layernorm ----------------
__global__ void ln_kernel(const float* __restrict__ x, const float* __restrict__ g,
                          const float* __restrict__ b, float* __restrict__ out) {
    __shared__ float red0[8], red1[8];
    int row = blockIdx.x;
    int tid = threadIdx.x;
    const float* xr = x + (size_t)row * CC;
    float s = 0.f, s2 = 0.f;
    for (int i = tid; i < CC; i += 256) { float v = xr[i]; s += v; s2 += v * v; }
    for (int o = 16; o; o >>= 1) {
        s  += __shfl_xor_sync(0xffffffffu, s,  o);
        s2 += __shfl_xor_sync(0xffffffffu, s2, o);
    }
    if ((tid & 31) == 0) { red0[tid >> 5] = s; red1[tid >> 5] = s2; }
    __syncthreads();
    if (tid < 32) {
        s  = (tid < 8) ? red0[tid] : 0.f;
        s2 = (tid < 8) ? red1[tid] : 0.f;
        for (int o = 4; o; o >>= 1) {
            s  += __shfl_xor_sync(0xffffffffu, s,  o);
            s2 += __shfl_xor_sync(0xffffffffu, s2, o);
        }
        if (tid == 0) { red0[0] = s; red1[0] = s2; }
    }
    __syncthreads();
    float mu  = red0[0] * (1.f / CC);
    float var = red1[0] * (1.f / CC) - mu * mu;
    float rs  = rsqrtf(var + EPS_LN);
    float* outr = out + (size_t)row * CC;
    for (int i = tid; i < CC; i += 256)
        outr[i] = (xr[i] - mu) * rs * g[i] + b[i];
}

// ---------------- cp.async helpers ----------------
__device__ __forceinline__ uint32_t smem_u32(const void* p) {
    uint32_t a;
    asm("{ .reg .u64 t; cvta.to.shared.u64 t, %1; cvt.u32.u64 %0, t; }" : "=r"(a) : "l"(p));
    return a;
}
__device__ __forceinline__ void cp_async16(uint32_t dst, const void* src) {
    asm volatile("cp.async.cg.shared.global [%0], [%1], 16;" :: "r"(dst), "l"(src));
}
#define CP_COMMIT() asm volatile("cp.async.commit_group;" ::: "memory")
template <int N>
__device__ __forceinline__ void cp_wait() {
    asm volatile("cp.async.wait_group %0;" :: "n"(N) : "memory");
}

__device__ __forceinline__ uint32_t f2tf32(float x) {
    uint32_t u;
    asm("cvt.rna.tf32.f32 %0, %1;" : "=r"(u) : "f"(x));
    return u;
}

// ---------------- tf32 mma.sync GEMM, cp.async 3-stage pipeline ----------------
// C[M,N] = A[M,K] @ W[K,N] (+bias, +resid / gelu).  W consumed row-major (no transpose).
// tile 128x128x16, 256 threads (8 warps), warp = 64x32, mma m16n8k8.
#define EPI_BIAS  0
#define EPI_RESID 1
#define EPI_GELU  2

#define STAGES 3
#define ASTR 20           // A stage row stride (words); 80B rows keep 16B align, conflict-free frags
#define BSTR 136          // B stage row stride (words); 136 % 32 == 8 -> conflict-free frags
#define A_STG (128 * ASTR)            // 2560 words
#define B_STG (16 * BSTR)             // 2176 words
#define GEMM_SMEM_WORDS (STAGES * (A_STG + B_STG) + 128)
#define GEMM_SMEM_BYTES (GEMM_SMEM_WORDS * 4)   // 57,344 B

template <int EPI>
__global__ __launch_bounds__(256)
void tc_gemm_kernel(const float* __restrict__ A, const float* __restrict__ W,
                    const float* __restrict__ bias, const float* __restrict__ resid,
                    float* __restrict__ C, int Ndim, int Kdim) {
    extern __shared__ float dsm[];
    float* sA = dsm;                                 // STAGES * A_STG
    float* sB = dsm + STAGES * A_STG;                // STAGES * B_STG
    float* sBias = dsm + STAGES * (A_STG + B_STG);   // 128

    int tid = threadIdx.x;
    int lane = tid & 31;
    int wid = tid >> 5;
    int bm = blockIdx.y * 128, bn = blockIdx.x * 128;

    if (tid < 128) sBias[tid] = bias[bn + tid];

    int lr = lane >> 2;    // 0..7
    int lc = lane & 3;     // 0..3
    int wm = (wid & 1) * 64;
    int wn = (wid >> 1) * 32;

    // cp.async mapping: 2 A-float4 + 2 B-float4 per thread per stage
    int aIdx0 = tid * 2, aIdx1 = tid * 2 + 1;            // 0..511
    int aRow0 = aIdx0 >> 2, aKg0 = (aIdx0 & 3) * 4;
    int aRow1 = aIdx1 >> 2, aKg1 = (aIdx1 & 3) * 4;
    int bKr0 = aIdx0 >> 5, bNg0 = (aIdx0 & 31) * 4;
    int bKr1 = aIdx1 >> 5, bNg1 = (aIdx1 & 31) * 4;

    uint32_t sA_base = smem_u32(sA);
    uint32_t sB_base = smem_u32(sB);

    const float* aSrc0 = A + (size_t)(bm + aRow0) * Kdim + aKg0;
    const float* aSrc1 = A + (size_t)(bm + aRow1) * Kdim + aKg1;
    const float* bSrc0 = W + (size_t)bKr0 * Ndim + bn + bNg0;
    const float* bSrc1 = W + (size_t)bKr1 * Ndim + bn + bNg1;

    float acc[4][4][4];
#pragma unroll
    for (int i = 0; i < 4; i++)
#pragma unroll
        for (int j = 0; j < 4; j++)
#pragma unroll
            for (int r = 0; r < 4; r++) acc[i][j][r] = 0.f;

    int nch = Kdim >> 4;

#define LOAD_STAGE(stg, chunk) do {                                                   \
        int _k0 = (chunk) << 4;                                                       \
        uint32_t _ab = sA_base + (uint32_t)((stg) * A_STG) * 4;                       \
        uint32_t _bb = sB_base + (uint32_t)((stg) * B_STG) * 4;                       \
        cp_async16(_ab + (uint32_t)(aRow0 * ASTR + aKg0) * 4, aSrc0 + _k0);           \
        cp_async16(_ab + (uint32_t)(aRow1 * ASTR + aKg1) * 4, aSrc1 + _k0);           \
        cp_async16(_bb + (uint32_t)(bKr0 * BSTR + bNg0) * 4, bSrc0 + (size_t)_k0 * Ndim); \
        cp_async16(_bb + (uint32_t)(bKr1 * BSTR + bNg1) * 4, bSrc1 + (size_t)_k0 * Ndim); \
    } while (0)

    // prologue: fill STAGES-1 stages
#pragma unroll
    for (int s = 0; s < STAGES - 1; s++) {
        if (s < nch) LOAD_STAGE(s, s);
        CP_COMMIT();
    }
    cp_wait<STAGES - 2>();
    __syncthreads();

    for (int c = 0; c < nch; c++) {
        int buf = c % STAGES;
        int nc = c + STAGES - 1;
        if (nc < nch) LOAD_STAGE(nc % STAGES, nc);
        CP_COMMIT();

        const uint32_t* As = (const uint32_t*)(sA + buf * A_STG);
        const uint32_t* Bs = (const uint32_t*)(sB + buf * B_STG);
#pragma unroll
        for (int ks = 0; ks < 2; ks++) {
            int k0 = ks * 8;
            uint32_t a[4][4], b[4][2];
#pragma unroll
            for (int i = 0; i < 4; i++) {
                int r0 = wm + i * 16 + lr;
                a[i][0] = f2tf32(__uint_as_float(As[r0 * ASTR + k0 + lc]));
                a[i][1] = f2tf32(__uint_as_float(As[(r0 + 8) * ASTR + k0 + lc]));
                a[i][2] = f2tf32(__uint_as_float(As[r0 * ASTR + k0 + lc + 4]));
                a[i][3] = f2tf32(__uint_as_float(As[(r0 + 8) * ASTR + k0 + lc + 4]));
            }
#pragma unroll
            for (int j = 0; j < 4; j++) {
                int n0 = wn + j * 8 + lr;
                b[j][0] = f2tf32(__uint_as_float(Bs[(k0 + lc) * BSTR + n0]));
                b[j][1] = f2tf32(__uint_as_float(Bs[(k0 + lc + 4) * BSTR + n0]));
            }
#pragma unroll
            for (int i = 0; i < 4; i++)
#pragma unroll
                for (int j = 0; j < 4; j++) {
                    asm volatile(
                        "mma.sync.aligned.m16n8k8.row.col.f32.tf32.tf32.f32 "
                        "{%0,%1,%2,%3}, {%4,%5,%6,%7}, {%8,%9}, {%0,%1,%2,%3};"
                        : "+f"(acc[i][j][0]), "+f"(acc[i][j][1]),
                          "+f"(acc[i][j][2]), "+f"(acc[i][j][3])
                        : "r"(a[i][0]), "r"(a[i][1]), "r"(a[i][2]), "r"(a[i][3]),
                          "r"(b[j][0]), "r"(b[j][1]));
                }
        }
        cp_wait<STAGES - 2>();
        __syncthreads();
    }
#undef LOAD_STAGE

    // epilogue
#pragma unroll
    for (int i = 0; i < 4; i++) {
        int r0 = bm + wm + i * 16 + lr;
#pragma unroll
        for (int j = 0; j < 4; j++) {
            int colL = wn + j * 8 + lc * 2;
            int col = bn + colL;
            float v0 = acc[i][j][0] + sBias[colL];
            float v1 = acc[i][j][1] + sBias[colL + 1];
            float v2 = acc[i][j][2] + sBias[colL];
            float v3 = acc[i][j][3] + sBias[colL + 1];
            if (EPI == EPI_RESID) {
                float2 ra = *(const float2*)(resid + (size_t)r0 * Ndim + col);
                float2 rb = *(const float2*)(resid + (size_t)(r0 + 8) * Ndim + col);
                v0 += ra.x; v1 += ra.y; v2 += rb.x; v3 += rb.y;
            }
            if (EPI == EPI_GELU) {
                v0 = v0 * 0.5f * (1.0f + erff(v0 * 0.70710678118654752f));
                v1 = v1 * 0.5f * (1.0f + erff(v1 * 0.70710678118654752f));
                v2 = v2 * 0.5f * (1.0f + erff(v2 * 0.70710678118654752f));
                v3 = v3 * 0.5f * (1.0f + erff(v3 * 0.70710678118654752f));
            }
            *(float2*)(C + (size_t)r0 * Ndim + col)       = make_float2(v0, v1);
            *(float2*)(C + (size_t)(r0 + 8) * Ndim + col) = make_float2(v2, v3);
        }
    }
}

// ---------------- fused attention (flash-style, 64 q-rows per block) ----------------
#define AT_STR 65
#define ATTN_SMEM ((4 * 64 * AT_STR + 3 * 64) * (int)sizeof(float))

__global__ __launch_bounds__(256)
void attn_kernel(const float* __restrict__ Q, const float* __restrict__ K,
                 const float* __restrict__ V, float* __restrict__ Y) {
    extern __shared__ float sm[];
    float* Qs = sm;
    float* Ks = Qs + 64 * AT_STR;
    float* Vs = Ks + 64 * AT_STR;
    float* Ps = Vs + 64 * AT_STR;
    float* mS = Ps + 64 * AT_STR;
    float* lS = mS + 64;
    float* aS = lS + 64;

    int tid = threadIdx.x;
    int qb  = blockIdx.x * 64;
    int bh  = blockIdx.y;
    int b   = bh / NH, h = bh % NH;
    size_t base = (size_t)b * TT * CC + (size_t)h * HD;

    for (int i = tid; i < 64 * 64; i += 256) {
        int r = i >> 6, d = i & 63;
        Qs[r * AT_STR + d] = Q[base + (size_t)(qb + r) * CC + d];
    }
    if (tid < 64) { mS[tid] = -1e30f; lS[tid] = 0.f; }

    int tx = tid & 15, ty = tid >> 4;
    float o[4][4];
#pragma unroll
    for (int i = 0; i < 4; i++)
#pragma unroll
        for (int j = 0; j < 4; j++) o[i][j] = 0.f;

    int qmod = qb & 255;
    int srow = tid >> 2, sseg = tid & 3;

    for (int kb = 0; kb < TT; kb += 64) {
        if ((kb & 255) > qmod + 63) continue;
        __syncthreads();
        for (int i = tid; i < 64 * 64; i += 256) {
            int r = i >> 6, d = i & 63;
            Ks[r * AT_STR + d] = K[base + (size_t)(kb + r) * CC + d];
            Vs[r * AT_STR + d] = V[base + (size_t)(kb + r) * CC + d];
        }
        __syncthreads();

        float s[4][4];
#pragma unroll
        for (int i = 0; i < 4; i++)
#pragma unroll
            for (int j = 0; j < 4; j++) s[i][j] = 0.f;
        for (int d = 0; d < 64; d++) {
            float a0 = Qs[(ty * 4 + 0) * AT_STR + d];
            float a1 = Qs[(ty * 4 + 1) * AT_STR + d];
            float a2 = Qs[(ty * 4 + 2) * AT_STR + d];
            float a3 = Qs[(ty * 4 + 3) * AT_STR + d];
            float c0 = Ks[(tx * 4 + 0) * AT_STR + d];
            float c1 = Ks[(tx * 4 + 1) * AT_STR + d];
            float c2 = Ks[(tx * 4 + 2) * AT_STR + d];
            float c3 = Ks[(tx * 4 + 3) * AT_STR + d];
            s[0][0] += a0 * c0; s[0][1] += a0 * c1; s[0][2] += a0 * c2; s[0][3] += a0 * c3;
            s[1][0] += a1 * c0; s[1][1] += a1 * c1; s[1][2] += a1 * c2; s[1][3] += a1 * c3;
            s[2][0] += a2 * c0; s[2][1] += a2 * c1; s[2][2] += a2 * c2; s[2][3] += a2 * c3;
            s[3][0] += a3 * c0; s[3][1] += a3 * c1; s[3][2] += a3 * c2; s[3][3] += a3 * c3;
        }
#pragma unroll
        for (int i = 0; i < 4; i++) {
            int qg = (qb + ty * 4 + i) & 255;
#pragma unroll
            for (int j = 0; j < 4; j++) {
                int kg = (kb + tx * 4 + j) & 255;
                float v = s[i][j] * 0.125f;
                if (kg > qg) v = -1e30f;
                Ps[(ty * 4 + i) * AT_STR + tx * 4 + j] = v;
            }
        }
        __syncthreads();

        {
            float mx = -1e30f;
            int rbase = srow * AT_STR + sseg * 16;
#pragma unroll
            for (int k2 = 0; k2 < 16; k2++) mx = fmaxf(mx, Ps[rbase + k2]);
            mx = fmaxf(mx, __shfl_xor_sync(0xffffffffu, mx, 1));
            mx = fmaxf(mx, __shfl_xor_sync(0xffffffffu, mx, 2));
            float m_old = mS[srow];
            float m_new = fmaxf(m_old, mx);
            float sum = 0.f;
#pragma unroll
            for (int k2 = 0; k2 < 16; k2++) {
                float p = __expf(Ps[rbase + k2] - m_new);
                Ps[rbase + k2] = p;
                sum += p;
            }
            sum += __shfl_xor_sync(0xffffffffu, sum, 1);
            sum += __shfl_xor_sync(0xffffffffu, sum, 2);
            if (sseg == 0) {
                float alpha = __expf(m_old - m_new);
                lS[srow] = lS[srow] * alpha + sum;
                mS[srow] = m_new;
                aS[srow] = alpha;
            }
        }
        __syncthreads();

#pragma unroll
        for (int i = 0; i < 4; i++) {
            float al = aS[ty * 4 + i];
#pragma unroll
            for (int j = 0; j < 4; j++) o[i][j] *= al;
        }
        for (int k2 = 0; k2 < 64; k2++) {
            float p0 = Ps[(ty * 4 + 0) * AT_STR + k2];
            float p1 = Ps[(ty * 4 + 1) * AT_STR + k2];
            float p2 = Ps[(ty * 4 + 2) * AT_STR + k2];
            float p3 = Ps[(ty * 4 + 3) * AT_STR + k2];
            float v0 = Vs[k2 * AT_STR + tx * 4 + 0];
            float v1 = Vs[k2 * AT_STR + tx * 4 + 1];
            float v2 = Vs[k2 * AT_STR + tx * 4 + 2];
            float v3 = Vs[k2 * AT_STR + tx * 4 + 3];
            o[0][0] += p0 * v0; o[0][1] += p0 * v1; o[0][2] += p0 * v2; o[0][3] += p0 * v3;
            o[1][0] += p1 * v0; o[1][1] += p1 * v1; o[1][2] += p1 * v2; o[1][3] += p1 * v3;
            o[2][0] += p2 * v0; o[2][1] += p2 * v1; o[2][2] += p2 * v2; o[2][3] += p2 * v3;
            o[3][0] += p3 * v0; o[3][1] += p3 * v1; o[3][2] += p3 * v2; o[3][3] += p3 * v3;
        }
    }

#pragma unroll
    for (int i = 0; i < 4; i++) {
        float inv = 1.0f / lS[ty * 4 + i];
        size_t rowoff = base + (size_t)(qb + ty * 4 + i) * CC + tx * 4;
#pragma unroll
        for (int j = 0; j < 4; j++) Y[rowoff + j] = o[i][j] * inv;
    }
}

// ---------------- host orchestration ----------------
extern "C" void kernel_launch(void* const* d_in, const int* in_sizes, int n_in,
                              void* d_out, int out_size) {
    const float* x     = (const float*)d_in[0];
    const float* ln1_g = (const float*)d_in[1];
    const float* ln1_b = (const float*)d_in[2];
    const float* Wq    = (const float*)d_in[3];
    const float* bq    = (const float*)d_in[4];
    const float* Wk    = (const float*)d_in[5];
    const float* bk    = (const float*)d_in[6];
    const float* Wv    = (const float*)d_in[7];
    const float* bv    = (const float*)d_in[8];
    const float* Wp    = (const float*)d_in[9];
    const float* bp    = (const float*)d_in[10];
    const float* ln2_g = (const float*)d_in[11];
    const float* ln2_b = (const float*)d_in[12];
    const float* W1    = (const float*)d_in[13];
    const float* b1    = (const float*)d_in[14];
    const float* W2    = (const float*)d_in[15];
    const float* b2    = (const float*)d_in[16];

    float *res, *ln, *q, *k, *v, *y, *h1;
    cudaGetSymbolAddress((void**)&res, g_res);
    cudaGetSymbolAddress((void**)&ln,  g_ln);
    cudaGetSymbolAddress((void**)&q,   g_q);
    cudaGetSymbolAddress((void**)&k,   g_k);
    cudaGetSymbolAddress((void**)&v,   g_v);
    cudaGetSymbolAddress((void**)&y,   g_y);
    cudaGetSymbolAddress((void**)&h1,  g_h1);

    cudaFuncSetAttribute(attn_kernel, cudaFuncAttributeMaxDynamicSharedMemorySize, ATTN_SMEM);
    cudaFuncSetAttribute(tc_gemm_kernel<EPI_BIAS>,  cudaFuncAttributeMaxDynamicSharedMemorySize, GEMM_SMEM_BYTES);
    cudaFuncSetAttribute(tc_gemm_kernel<EPI_RESID>, cudaFuncAttributeMaxDynamicSharedMemorySize, GEMM_SMEM_BYTES);
    cudaFuncSetAttribute(tc_gemm_kernel<EPI_GELU>,  cudaFuncAttributeMaxDynamicSharedMemorySize, GEMM_SMEM_BYTES);

    // residual = x
    {
        int n4 = (MM * CC) / 4;
        copy4_kernel<<<(n4 + 255) / 256, 256>>>((float4*)res, (const float4*)x, n4);
    }

    dim3 gemm_qkv(CC / 128, MM / 128);      // 6 x 32
    dim3 gemm_h  (HID / 128, MM / 128);     // 24 x 32
    dim3 attn_grid(TT / 64, BB * NH);       // 16 x 48

    for (int l = 0; l < LNUM; l++) {
        const float* wq = Wq + (size_t)l * CC * CC;
        const float* wk = Wk + (size_t)l * CC * CC;
        const float* wv = Wv + (size_t)l * CC * CC;
        const float* wp = Wp + (size_t)l * CC * CC;
        const float* w1 = W1 + (size_t)l * CC * HID;
        const float* w2 = W2 + (size_t)l * HID * CC;

        ln_kernel<<<MM, 256>>>(res, ln1_g + (size_t)l*CC, ln1_b + (size_t)l*CC, ln);
        tc_gemm_kernel<EPI_BIAS><<<gemm_qkv, 256, GEMM_SMEM_BYTES>>>(ln, wq, bq + (size_t)l*CC, nullptr, q, CC, CC);
        tc_gemm_kernel<EPI_BIAS><<<gemm_qkv, 256, GEMM_SMEM_BYTES>>>(ln, wk, bk + (size_t)l*CC, nullptr, k, CC, CC);
        tc_gemm_kernel<EPI_BIAS><<<gemm_qkv, 256, GEMM_SMEM_BYTES>>>(ln, wv, bv + (size_t)l*CC, nullptr, v, CC, CC);
        attn_kernel<<<attn_grid, 256, ATTN_SMEM>>>(q, k, v, y);
        tc_gemm_kernel<EPI_RESID><<<gemm_qkv, 256, GEMM_SMEM_BYTES>>>(y, wp, bp + (size_t)l*CC, res, res, CC, CC);
        ln_kernel<<<MM, 256>>>(res, ln2_g + (size_t)l*CC, ln2_b + (size_t)l*CC, ln);
        tc_gemm_kernel<EPI_GELU><<<gemm_h, 256, GEMM_SMEM_BYTES>>>(ln, w1, b1 + (size_t)l*HID, nullptr, h1, HID, CC);
        tc_gemm_kernel<EPI_RESID><<<gemm_qkv, 256, GEMM_SMEM_BYTES>>>(h1, w2, b2 + (size_t)l*CC, res, res, CC, HID);
    }

    {
        int n4 = (MM * CC) / 4;
        copy4_kernel<<<(n4 + 255) / 256, 256>>>((float4*)d_out, (const float4*)res, n4);
    }
}

// round 5
// speedup vs baseline: 2.9894x; 1.3736x over previous
#include <cuda_runtime.h>
#include <math.h>
#include <cstdint>

// ---------------- problem constants ----------------
#define LNUM 4
#define BB   4
#define TT   1024
#define CC   768
#define NH   12
#define HD   64
#define HID  3072
#define MM   (BB*TT)          // 4096 rows
#define EPS_LN 1e-5f

// ---------------- scratch (device globals; no allocation allowed) ----------------
__device__ float g_res[(size_t)MM*CC];
__device__ float g_ln [(size_t)MM*CC];
__device__ float g_q  [(size_t)MM*CC];
__device__ float g_k  [(size_t)MM*CC];
__device__ float g_v  [(size_t)MM*CC];
__device__ float g_y  [(size_t)MM*CC];
__device__ float g_h1 [(size_t)MM*HID];

// ---------------- copy kernel (float4) ----------------
__global__ void copy4_kernel(float4* __restrict__ dst, const float4* __restrict__ src, int n4) {
    int i = blockIdx.x * blockDim.x + threadIdx.x;
    if (i < n4) dst[i] = src[i];
}

// ---------------- layernorm ----------------
__global__ void ln_kernel(const float* __restrict__ x, const float* __restrict__ g,
                          const float* __restrict__ b, float* __restrict__ out) {
    __shared__ float red0[8], red1[8];
    int row = blockIdx.x;
    int tid = threadIdx.x;
    const float* xr = x + (size_t)row * CC;
    float s = 0.f, s2 = 0.f;
    for (int i = tid; i < CC; i += 256) { float v = xr[i]; s += v; s2 += v * v; }
    for (int o = 16; o; o >>= 1) {
        s  += __shfl_xor_sync(0xffffffffu, s,  o);
        s2 += __shfl_xor_sync(0xffffffffu, s2, o);
    }
    if ((tid & 31) == 0) { red0[tid >> 5] = s; red1[tid >> 5] = s2; }
    __syncthreads();
    if (tid < 32) {
        s  = (tid < 8) ? red0[tid] : 0.f;
        s2 = (tid < 8) ? red1[tid] : 0.f;
        for (int o = 4; o; o >>= 1) {
            s  += __shfl_xor_sync(0xffffffffu, s,  o);
            s2 += __shfl_xor_sync(0xffffffffu, s2, o);
        }
        if (tid == 0) { red0[0] = s; red1[0] = s2; }
    }
    __syncthreads();
    float mu  = red0[0] * (1.f / CC);
    float var = red1[0] * (1.f / CC) - mu * mu;
    float rs  = rsqrtf(var + EPS_LN);
    float* outr = out + (size_t)row * CC;
    for (int i = tid; i < CC; i += 256)
        outr[i] = (xr[i] - mu) * rs * g[i] + b[i];
}

// ---------------- helpers ----------------
__device__ __forceinline__ uint32_t smem_u32(const void* p) {
    uint32_t a;
    asm("{ .reg .u64 t; cvta.to.shared.u64 t, %1; cvt.u32.u64 %0, t; }" : "=r"(a) : "l"(p));
    return a;
}
__device__ __forceinline__ void cp_async16(uint32_t dst, const void* src) {
    asm volatile("cp.async.cg.shared.global [%0], [%1], 16;" :: "r"(dst), "l"(src));
}
#define CP_COMMIT() asm volatile("cp.async.commit_group;" ::: "memory")
template <int N>
__device__ __forceinline__ void cp_wait() {
    asm volatile("cp.async.wait_group %0;" :: "n"(N) : "memory");
}
__device__ __forceinline__ uint32_t f2tf32(float x) {
    uint32_t u;
    asm("cvt.rna.tf32.f32 %0, %1;" : "=r"(u) : "f"(x));
    return u;
}
__device__ __forceinline__ void mma_tf32(float* d, uint32_t a0, uint32_t a1, uint32_t a2,
                                         uint32_t a3, uint32_t b0, uint32_t b1) {
    asm volatile(
        "mma.sync.aligned.m16n8k8.row.col.f32.tf32.tf32.f32 "
        "{%0,%1,%2,%3}, {%4,%5,%6,%7}, {%8,%9}, {%0,%1,%2,%3};"
        : "+f"(d[0]), "+f"(d[1]), "+f"(d[2]), "+f"(d[3])
        : "r"(a0), "r"(a1), "r"(a2), "r"(a3), "r"(b0), "r"(b1));
}

// ---------------- tf32 mma.sync GEMM, cp.async 3-stage pipeline ----------------
#define EPI_BIAS  0
#define EPI_RESID 1
#define EPI_GELU  2

#define STAGES 3
#define ASTR 20
#define BSTR 136
#define A_STG (128 * ASTR)
#define B_STG (16 * BSTR)
#define GEMM_SMEM_WORDS (STAGES * (A_STG + B_STG) + 128)
#define GEMM_SMEM_BYTES (GEMM_SMEM_WORDS * 4)

template <int EPI>
__device__ __forceinline__ void gemm_body(const float* __restrict__ A, const float* __restrict__ W,
                                          const float* __restrict__ bias, const float* __restrict__ resid,
                                          float* __restrict__ C, int Ndim, int Kdim,
                                          int bm, int bn, float* dsm) {
    float* sA = dsm;
    float* sB = dsm + STAGES * A_STG;
    float* sBias = dsm + STAGES * (A_STG + B_STG);

    int tid = threadIdx.x;
    int lane = tid & 31;
    int wid = tid >> 5;

    if (tid < 128) sBias[tid] = bias[bn + tid];

    int lr = lane >> 2;
    int lc = lane & 3;
    int wm = (wid & 1) * 64;
    int wn = (wid >> 1) * 32;

    int aIdx0 = tid * 2, aIdx1 = tid * 2 + 1;
    int aRow0 = aIdx0 >> 2, aKg0 = (aIdx0 & 3) * 4;
    int aRow1 = aIdx1 >> 2, aKg1 = (aIdx1 & 3) * 4;
    int bKr0 = aIdx0 >> 5, bNg0 = (aIdx0 & 31) * 4;
    int bKr1 = aIdx1 >> 5, bNg1 = (aIdx1 & 31) * 4;

    uint32_t sA_base = smem_u32(sA);
    uint32_t sB_base = smem_u32(sB);

    const float* aSrc0 = A + (size_t)(bm + aRow0) * Kdim + aKg0;
    const float* aSrc1 = A + (size_t)(bm + aRow1) * Kdim + aKg1;
    const float* bSrc0 = W + (size_t)bKr0 * Ndim + bn + bNg0;
    const float* bSrc1 = W + (size_t)bKr1 * Ndim + bn + bNg1;

    float acc[4][4][4];
#pragma unroll
    for (int i = 0; i < 4; i++)
#pragma unroll
        for (int j = 0; j < 4; j++)
#pragma unroll
            for (int r = 0; r < 4; r++) acc[i][j][r] = 0.f;

    int nch = Kdim >> 4;

#define LOAD_STAGE(stg, chunk) do {                                                   \
        int _k0 = (chunk) << 4;                                                       \
        uint32_t _ab = sA_base + (uint32_t)((stg) * A_STG) * 4;                       \
        uint32_t _bb = sB_base + (uint32_t)((stg) * B_STG) * 4;                       \
        cp_async16(_ab + (uint32_t)(aRow0 * ASTR + aKg0) * 4, aSrc0 + _k0);           \
        cp_async16(_ab + (uint32_t)(aRow1 * ASTR + aKg1) * 4, aSrc1 + _k0);           \
        cp_async16(_bb + (uint32_t)(bKr0 * BSTR + bNg0) * 4, bSrc0 + (size_t)_k0 * Ndim); \
        cp_async16(_bb + (uint32_t)(bKr1 * BSTR + bNg1) * 4, bSrc1 + (size_t)_k0 * Ndim); \
    } while (0)

#pragma unroll
    for (int s = 0; s < STAGES - 1; s++) {
        if (s < nch) LOAD_STAGE(s, s);
        CP_COMMIT();
    }
    cp_wait<STAGES - 2>();
    __syncthreads();

    for (int c = 0; c < nch; c++) {
        int buf = c % STAGES;
        int nc = c + STAGES - 1;
        if (nc < nch) LOAD_STAGE(nc % STAGES, nc);
        CP_COMMIT();

        const uint32_t* As = (const uint32_t*)(sA + buf * A_STG);
        const uint32_t* Bs = (const uint32_t*)(sB + buf * B_STG);
#pragma unroll
        for (int ks = 0; ks < 2; ks++) {
            int k0 = ks * 8;
            uint32_t a[4][4], b[4][2];
#pragma unroll
            for (int i = 0; i < 4; i++) {
                int r0 = wm + i * 16 + lr;
                a[i][0] = f2tf32(__uint_as_float(As[r0 * ASTR + k0 + lc]));
                a[i][1] = f2tf32(__uint_as_float(As[(r0 + 8) * ASTR + k0 + lc]));
                a[i][2] = f2tf32(__uint_as_float(As[r0 * ASTR + k0 + lc + 4]));
                a[i][3] = f2tf32(__uint_as_float(As[(r0 + 8) * ASTR + k0 + lc + 4]));
            }
#pragma unroll
            for (int j = 0; j < 4; j++) {
                int n0 = wn + j * 8 + lr;
                b[j][0] = f2tf32(__uint_as_float(Bs[(k0 + lc) * BSTR + n0]));
                b[j][1] = f2tf32(__uint_as_float(Bs[(k0 + lc + 4) * BSTR + n0]));
            }
#pragma unroll
            for (int i = 0; i < 4; i++)
#pragma unroll
                for (int j = 0; j < 4; j++)
                    mma_tf32(acc[i][j], a[i][0], a[i][1], a[i][2], a[i][3], b[j][0], b[j][1]);
        }
        cp_wait<STAGES - 2>();
        __syncthreads();
    }
#undef LOAD_STAGE

#pragma unroll
    for (int i = 0; i < 4; i++) {
        int r0 = bm + wm + i * 16 + lr;
#pragma unroll
        for (int j = 0; j < 4; j++) {
            int colL = wn + j * 8 + lc * 2;
            int col = bn + colL;
            float v0 = acc[i][j][0] + sBias[colL];
            float v1 = acc[i][j][1] + sBias[colL + 1];
            float v2 = acc[i][j][2] + sBias[colL];
            float v3 = acc[i][j][3] + sBias[colL + 1];
            if (EPI == EPI_RESID) {
                float2 ra = *(const float2*)(resid + (size_t)r0 * Ndim + col);
                float2 rb = *(const float2*)(resid + (size_t)(r0 + 8) * Ndim + col);
                v0 += ra.x; v1 += ra.y; v2 += rb.x; v3 += rb.y;
            }
            if (EPI == EPI_GELU) {
                v0 = v0 * 0.5f * (1.0f + erff(v0 * 0.70710678118654752f));
                v1 = v1 * 0.5f * (1.0f + erff(v1 * 0.70710678118654752f));
                v2 = v2 * 0.5f * (1.0f + erff(v2 * 0.70710678118654752f));
                v3 = v3 * 0.5f * (1.0f + erff(v3 * 0.70710678118654752f));
            }
            *(float2*)(C + (size_t)r0 * Ndim + col)       = make_float2(v0, v1);
            *(float2*)(C + (size_t)(r0 + 8) * Ndim + col) = make_float2(v2, v3);
        }
    }
}

template <int EPI>
__global__ __launch_bounds__(256)
void tc_gemm_kernel(const float* __restrict__ A, const float* __restrict__ W,
                    const float* __restrict__ bias, const float* __restrict__ resid,
                    float* __restrict__ C, int Ndim, int Kdim) {
    extern __shared__ float dsm[];
    gemm_body<EPI>(A, W, bias, resid, C, Ndim, Kdim, blockIdx.y * 128, blockIdx.x * 128, dsm);
}

// merged QKV: blockIdx.z selects among (Wq,bq,q), (Wk,bk,k), (Wv,bv,v)
__global__ __launch_bounds__(256)
void qkv_gemm_kernel(const float* __restrict__ A,
                     const float* __restrict__ W0, const float* __restrict__ W1, const float* __restrict__ W2,
                     const float* __restrict__ b0, const float* __restrict__ b1, const float* __restrict__ b2,
                     float* __restrict__ C0, float* __restrict__ C1, float* __restrict__ C2) {
    extern __shared__ float dsm[];
    const float* W = (blockIdx.z == 0) ? W0 : (blockIdx.z == 1) ? W1 : W2;
    const float* bi = (blockIdx.z == 0) ? b0 : (blockIdx.z == 1) ? b1 : b2;
    float* C = (blockIdx.z == 0) ? C0 : (blockIdx.z == 1) ? C1 : C2;
    gemm_body<EPI_BIAS>(A, W, bi, nullptr, C, CC, CC, blockIdx.y * 128, blockIdx.x * 128, dsm);
}

// ---------------- tensor-core flash attention ----------------
// block: 128 q-rows of one (b,h); 8 warps, warp w owns rows w*16..w*16+15.
// S = Q K^T and O += P V via m16n8k8 tf32 mma. Online softmax in registers.
#define QSTR 68
#define KSTR 68
#define VSTR 72
#define PSTR 68
#define ATT_Q_OFF 0
#define ATT_K_OFF (128 * QSTR)
#define ATT_V_OFF (ATT_K_OFF + 64 * KSTR)
#define ATT_P_OFF (ATT_V_OFF + 64 * VSTR)
#define ATT_M_OFF (ATT_P_OFF + 128 * PSTR)
#define ATT_L_OFF (ATT_M_OFF + 128)
#define ATTN_SMEM_WORDS (ATT_L_OFF + 128)
#define ATTN_SMEM (ATTN_SMEM_WORDS * (int)sizeof(float))

__global__ __launch_bounds__(256)
void attn_tc_kernel(const float* __restrict__ Q, const float* __restrict__ K,
                    const float* __restrict__ V, float* __restrict__ Y) {
    extern __shared__ float sm[];
    float* Qs = sm + ATT_Q_OFF;
    float* Ks = sm + ATT_K_OFF;
    float* Vs = sm + ATT_V_OFF;
    float* Ps = sm + ATT_P_OFF;
    float* mS = sm + ATT_M_OFF;
    float* lS = sm + ATT_L_OFF;

    int tid = threadIdx.x;
    int lane = tid & 31;
    int wid = tid >> 5;
    int lr = lane >> 2;
    int lc = lane & 3;
    int wr = wid * 16;

    int qb = blockIdx.x * 128;
    int bh = blockIdx.y;
    int b = bh / NH, h = bh % NH;
    size_t base = (size_t)b * TT * CC + (size_t)h * HD;

    // load Q tile (prescaled by 1/sqrt(hd))
    for (int i = tid; i < 128 * 16; i += 256) {
        int row = i >> 4, cg = (i & 15) * 4;
        float4 qv = *(const float4*)(Q + base + (size_t)(qb + row) * CC + cg);
        *(float4*)(Qs + row * QSTR + cg) =
            make_float4(qv.x * 0.125f, qv.y * 0.125f, qv.z * 0.125f, qv.w * 0.125f);
    }
    if (tid < 128) { mS[tid] = -1e30f; lS[tid] = 0.f; }

    float o[8][4];
#pragma unroll
    for (int j = 0; j < 8; j++)
#pragma unroll
        for (int r = 0; r < 4; r++) o[j][r] = 0.f;

    int qmod = qb & 255;
    int rm0 = qmod + wr + lr;       // row (mod 256) for first accum row
    int rm1 = rm0 + 8;

    for (int kb = 0; kb < TT; kb += 64) {
        int kbm = kb & 255;
        if (kbm > qmod + 127) continue;
        __syncthreads();
        for (int i = tid; i < 64 * 16; i += 256) {
            int row = i >> 4, cg = (i & 15) * 4;
            *(float4*)(Ks + row * KSTR + cg) = *(const float4*)(K + base + (size_t)(kb + row) * CC + cg);
            *(float4*)(Vs + row * VSTR + cg) = *(const float4*)(V + base + (size_t)(kb + row) * CC + cg);
        }
        __syncthreads();

        // ---- S = Q K^T ----
        float sacc[8][4];
#pragma unroll
        for (int j = 0; j < 8; j++)
#pragma unroll
            for (int r = 0; r < 4; r++) sacc[j][r] = 0.f;
#pragma unroll
        for (int ks = 0; ks < 8; ks++) {
            int k0 = ks * 8;
            uint32_t a0 = f2tf32(Qs[(wr + lr) * QSTR + k0 + lc]);
            uint32_t a1 = f2tf32(Qs[(wr + lr + 8) * QSTR + k0 + lc]);
            uint32_t a2 = f2tf32(Qs[(wr + lr) * QSTR + k0 + lc + 4]);
            uint32_t a3 = f2tf32(Qs[(wr + lr + 8) * QSTR + k0 + lc + 4]);
#pragma unroll
            for (int j = 0; j < 8; j++) {
                int n0 = j * 8 + lr;
                uint32_t b0 = f2tf32(Ks[n0 * KSTR + k0 + lc]);
                uint32_t b1 = f2tf32(Ks[n0 * KSTR + k0 + lc + 4]);
                mma_tf32(sacc[j], a0, a1, a2, a3, b0, b1);
            }
        }

        // ---- mask + online softmax ----
        float m0 = -1e30f, m1 = -1e30f;
#pragma unroll
        for (int j = 0; j < 8; j++) {
            int c0 = kbm + j * 8 + 2 * lc;
            if (c0 > rm0)     sacc[j][0] = -1e30f;
            if (c0 + 1 > rm0) sacc[j][1] = -1e30f;
            if (c0 > rm1)     sacc[j][2] = -1e30f;
            if (c0 + 1 > rm1) sacc[j][3] = -1e30f;
            m0 = fmaxf(m0, fmaxf(sacc[j][0], sacc[j][1]));
            m1 = fmaxf(m1, fmaxf(sacc[j][2], sacc[j][3]));
        }
        m0 = fmaxf(m0, __shfl_xor_sync(0xffffffffu, m0, 1));
        m0 = fmaxf(m0, __shfl_xor_sync(0xffffffffu, m0, 2));
        m1 = fmaxf(m1, __shfl_xor_sync(0xffffffffu, m1, 1));
        m1 = fmaxf(m1, __shfl_xor_sync(0xffffffffu, m1, 2));

        int r0 = wr + lr, r1 = r0 + 8;
        float mo0 = mS[r0], mo1 = mS[r1];
        float mn0 = fmaxf(mo0, m0), mn1 = fmaxf(mo1, m1);
        float al0 = __expf(mo0 - mn0), al1 = __expf(mo1 - mn1);

        float sum0 = 0.f, sum1 = 0.f;
#pragma unroll
        for (int j = 0; j < 8; j++) {
            float p00 = __expf(sacc[j][0] - mn0);
            float p01 = __expf(sacc[j][1] - mn0);
            float p10 = __expf(sacc[j][2] - mn1);
            float p11 = __expf(sacc[j][3] - mn1);
            sum0 += p00 + p01;
            sum1 += p10 + p11;
            *(float2*)(Ps + r0 * PSTR + j * 8 + 2 * lc) = make_float2(p00, p01);
            *(float2*)(Ps + r1 * PSTR + j * 8 + 2 * lc) = make_float2(p10, p11);
            // rescale O accumulators
            o[j][0] *= al0; o[j][1] *= al0; o[j][2] *= al1; o[j][3] *= al1;
        }
        sum0 += __shfl_xor_sync(0xffffffffu, sum0, 1);
        sum0 += __shfl_xor_sync(0xffffffffu, sum0, 2);
        sum1 += __shfl_xor_sync(0xffffffffu, sum1, 1);
        sum1 += __shfl_xor_sync(0xffffffffu, sum1, 2);
        if (lc == 0) {
            lS[r0] = lS[r0] * al0 + sum0;
            lS[r1] = lS[r1] * al1 + sum1;
            mS[r0] = mn0;
            mS[r1] = mn1;
        }
        __syncwarp();

        // ---- O += P V ----
#pragma unroll
        for (int ks = 0; ks < 8; ks++) {
            int k0 = ks * 8;
            uint32_t a0 = f2tf32(Ps[(wr + lr) * PSTR + k0 + lc]);
            uint32_t a1 = f2tf32(Ps[(wr + lr + 8) * PSTR + k0 + lc]);
            uint32_t a2 = f2tf32(Ps[(wr + lr) * PSTR + k0 + lc + 4]);
            uint32_t a3 = f2tf32(Ps[(wr + lr + 8) * PSTR + k0 + lc + 4]);
#pragma unroll
            for (int j = 0; j < 8; j++) {
                int n0 = j * 8 + lr;
                uint32_t b0 = f2tf32(Vs[(k0 + lc) * VSTR + n0]);
                uint32_t b1 = f2tf32(Vs[(k0 + lc + 4) * VSTR + n0]);
                mma_tf32(o[j], a0, a1, a2, a3, b0, b1);
            }
        }
    }

    __syncwarp();
    int r0 = wr + lr, r1 = r0 + 8;
    float inv0 = 1.0f / lS[r0];
    float inv1 = 1.0f / lS[r1];
#pragma unroll
    for (int j = 0; j < 8; j++) {
        int d = j * 8 + 2 * lc;
        *(float2*)(Y + base + (size_t)(qb + r0) * CC + d) = make_float2(o[j][0] * inv0, o[j][1] * inv0);
        *(float2*)(Y + base + (size_t)(qb + r1) * CC + d) = make_float2(o[j][2] * inv1, o[j][3] * inv1);
    }
}

// ---------------- host orchestration ----------------
extern "C" void kernel_launch(void* const* d_in, const int* in_sizes, int n_in,
                              void* d_out, int out_size) {
    const float* x     = (const float*)d_in[0];
    const float* ln1_g = (const float*)d_in[1];
    const float* ln1_b = (const float*)d_in[2];
    const float* Wq    = (const float*)d_in[3];
    const float* bq    = (const float*)d_in[4];
    const float* Wk    = (const float*)d_in[5];
    const float* bk    = (const float*)d_in[6];
    const float* Wv    = (const float*)d_in[7];
    const float* bv    = (const float*)d_in[8];
    const float* Wp    = (const float*)d_in[9];
    const float* bp    = (const float*)d_in[10];
    const float* ln2_g = (const float*)d_in[11];
    const float* ln2_b = (const float*)d_in[12];
    const float* W1    = (const float*)d_in[13];
    const float* b1    = (const float*)d_in[14];
    const float* W2    = (const float*)d_in[15];
    const float* b2    = (const float*)d_in[16];

    float *res, *ln, *q, *k, *v, *y, *h1;
    cudaGetSymbolAddress((void**)&res, g_res);
    cudaGetSymbolAddress((void**)&ln,  g_ln);
    cudaGetSymbolAddress((void**)&q,   g_q);
    cudaGetSymbolAddress((void**)&k,   g_k);
    cudaGetSymbolAddress((void**)&v,   g_v);
    cudaGetSymbolAddress((void**)&y,   g_y);
    cudaGetSymbolAddress((void**)&h1,  g_h1);

    cudaFuncSetAttribute(attn_tc_kernel, cudaFuncAttributeMaxDynamicSharedMemorySize, ATTN_SMEM);
    cudaFuncSetAttribute(tc_gemm_kernel<EPI_BIAS>,  cudaFuncAttributeMaxDynamicSharedMemorySize, GEMM_SMEM_BYTES);
    cudaFuncSetAttribute(tc_gemm_kernel<EPI_RESID>, cudaFuncAttributeMaxDynamicSharedMemorySize, GEMM_SMEM_BYTES);
    cudaFuncSetAttribute(tc_gemm_kernel<EPI_GELU>,  cudaFuncAttributeMaxDynamicSharedMemorySize, GEMM_SMEM_BYTES);
    cudaFuncSetAttribute(qkv_gemm_kernel,           cudaFuncAttributeMaxDynamicSharedMemorySize, GEMM_SMEM_BYTES);

    // residual = x
    {
        int n4 = (MM * CC) / 4;
        copy4_kernel<<<(n4 + 255) / 256, 256>>>((float4*)res, (const float4*)x, n4);
    }

    dim3 gemm_qkv3(CC / 128, MM / 128, 3);  // 6 x 32 x 3 = 576 blocks
    dim3 gemm_c  (CC / 128, MM / 128);      // 6 x 32
    dim3 gemm_h  (HID / 128, MM / 128);     // 24 x 32
    dim3 attn_grid(TT / 128, BB * NH);      // 8 x 48

    for (int l = 0; l < LNUM; l++) {
        const float* wq = Wq + (size_t)l * CC * CC;
        const float* wk = Wk + (size_t)l * CC * CC;
        const float* wv = Wv + (size_t)l * CC * CC;
        const float* wp = Wp + (size_t)l * CC * CC;
        const float* w1 = W1 + (size_t)l * CC * HID;
        const float* w2 = W2 + (size_t)l * HID * CC;

        ln_kernel<<<MM, 256>>>(res, ln1_g + (size_t)l*CC, ln1_b + (size_t)l*CC, ln);
        qkv_gemm_kernel<<<gemm_qkv3, 256, GEMM_SMEM_BYTES>>>(
            ln, wq, wk, wv, bq + (size_t)l*CC, bk + (size_t)l*CC, bv + (size_t)l*CC, q, k, v);
        attn_tc_kernel<<<attn_grid, 256, ATTN_SMEM>>>(q, k, v, y);
        tc_gemm_kernel<EPI_RESID><<<gemm_c, 256, GEMM_SMEM_BYTES>>>(y, wp, bp + (size_t)l*CC, res, res, CC, CC);
        ln_kernel<<<MM, 256>>>(res, ln2_g + (size_t)l*CC, ln2_b + (size_t)l*CC, ln);
        tc_gemm_kernel<EPI_GELU><<<gemm_h, 256, GEMM_SMEM_BYTES>>>(ln, w1, b1 + (size_t)l*HID, nullptr, h1, HID, CC);
        tc_gemm_kernel<EPI_RESID><<<gemm_c, 256, GEMM_SMEM_BYTES>>>(h1, w2, b2 + (size_t)l*CC, res, res, CC, HID);
    }

    {
        int n4 = (MM * CC) / 4;
        copy4_kernel<<<(n4 + 255) / 256, 256>>>((float4*)d_out, (const float4*)res, n4);
    }
}